// round 1
// baseline (speedup 1.0000x reference)
#include <cuda_runtime.h>

#define NG 512   // total groups (4 * 4096/32)
#define TG 32    // tokens per group
#define DD 1024  // model dim
#define NE 32    // experts
#define NS 128   // expert hidden size

__device__ float g_w[NG * NE];
__device__ int   g_sel[NG * NE];
__device__ float g_inner[(size_t)NE * NG * NS];  // 8 MB scratch

// ---- packed f32x2 helpers (FFMA2 only reachable via PTX) ----
static __device__ __forceinline__ unsigned long long pack2(float lo, float hi) {
    unsigned long long r;
    asm("mov.b64 %0, {%1, %2};" : "=l"(r) : "f"(lo), "f"(hi));
    return r;
}
static __device__ __forceinline__ void fma2(unsigned long long &d,
                                            unsigned long long a,
                                            unsigned long long b) {
    asm("fma.rn.f32x2 %0, %1, %2, %0;" : "+l"(d) : "l"(a), "l"(b));
}
static __device__ __forceinline__ float2 unpack2(unsigned long long v) {
    float lo, hi;
    asm("mov.b64 {%0, %1}, %2;" : "=f"(lo), "=f"(hi) : "l"(v));
    return make_float2(lo, hi);
}

// ---------------------------------------------------------------------------
// Router: per group, logits L[t][e] = x[t,:]·C[:,e] + t*step, then per-expert
// argmax over t and softmax weight w = 1/sum_t exp(L[t]-L[max]).
// ---------------------------------------------------------------------------
__global__ __launch_bounds__(256, 2) void router_kernel(
    const float* __restrict__ x, const float* __restrict__ ctrl)
{
    __shared__ __align__(16) float xs[TG][128];
    __shared__ float Ls[TG][NE];
    int g   = blockIdx.x;
    int tid = threadIdx.x;
    int e   = tid & 31;
    int tq  = tid >> 5;               // 0..7 -> tokens tq, tq+8, tq+16, tq+24
    const float* xg = x + (size_t)g * TG * DD;
    float acc0 = 0.f, acc1 = 0.f, acc2 = 0.f, acc3 = 0.f;

    for (int dc = 0; dc < DD; dc += 128) {
#pragma unroll
        for (int r = 0; r < 4; r++) {
            int j   = tid + r * 256;
            int row = j >> 5;
            int c4  = (j & 31) << 2;
            *(float4*)&xs[row][c4] =
                *(const float4*)(xg + (size_t)row * DD + dc + c4);
        }
        __syncthreads();
#pragma unroll 4
        for (int d = 0; d < 128; d++) {
            float c = __ldg(&ctrl[(size_t)(dc + d) * NE + e]);
            acc0 += xs[tq     ][d] * c;
            acc1 += xs[tq +  8][d] * c;
            acc2 += xs[tq + 16][d] * c;
            acc3 += xs[tq + 24][d] * c;
        }
        __syncthreads();
    }

    const float step = 1e-6f / 31.0f;  // jnp.linspace(0, 1e-6, 32) increments
    Ls[tq     ][e] = acc0 + (float)(tq     ) * step;
    Ls[tq +  8][e] = acc1 + (float)(tq +  8) * step;
    Ls[tq + 16][e] = acc2 + (float)(tq + 16) * step;
    Ls[tq + 24][e] = acc3 + (float)(tq + 24) * step;
    __syncthreads();

    if (tid < NE) {
        float m = Ls[0][tid];
        int am = 0;
#pragma unroll
        for (int t = 1; t < TG; t++) {
            float v = Ls[t][tid];
            if (v > m) { m = v; am = t; }
        }
        float s = 0.f;
#pragma unroll
        for (int t = 0; t < TG; t++) s += __expf(Ls[t][tid] - m);
        g_w[g * NE + tid]   = 1.0f / s;
        g_sel[g * NE + tid] = am;
    }
}

// ---------------------------------------------------------------------------
// FF1: per expert e, INNER[g,s] = relu( (w[g,e]*x[token(g,e),:]) @ f1[:,e,:] + f1b[e,:] )
// Batched GEMM M=512 K=1024 N=128, A rows gathered+scaled at load.
// Block tile 64x128, BK=16, 256 threads, 4x8 micro-tile in f32x2.
// ---------------------------------------------------------------------------
__global__ __launch_bounds__(256, 2) void gemm1_kernel(
    const float* __restrict__ x, const float* __restrict__ f1,
    const float* __restrict__ f1b)
{
    const int BM = 64, BN = 128, BK = 16;
    __shared__ __align__(16) float As[BK][BM];
    __shared__ __align__(16) float Bs[BK][BN];
    int e     = blockIdx.y;
    int gbase = blockIdx.x * BM;
    int tid   = threadIdx.x;

    // A loader: each thread owns one gathered row segment
    int lm  = tid & 63;
    int lkh = (tid >> 6) << 2;       // k offset 0,4,8,12
    int gg  = gbase + lm;
    float wv = g_w[gg * NE + e];
    const float* arow = x + (size_t)(gg * TG + g_sel[gg * NE + e]) * DD;

    // B loader: f1[k, e, n] rows (stride NE*NS), contiguous in n
    int bf  = tid << 1;
    int bk0 = bf >> 5;
    int bn0 = (bf & 31) << 2;
    const float* bbase = f1 + (size_t)e * NS;

    unsigned long long acc[4][4];
#pragma unroll
    for (int i = 0; i < 4; i++)
#pragma unroll
        for (int j = 0; j < 4; j++) acc[i][j] = 0ULL;

    int mt = (tid >> 4) << 2;        // 0..60
    int nt = (tid & 15) << 3;        // 0..120

    float4 pa  = *(const float4*)(arow + lkh);
    float4 pb0 = *(const float4*)(bbase + (size_t)bk0 * (NE * NS) + bn0);
    float4 pb1 = *(const float4*)(bbase + (size_t)bk0 * (NE * NS) + bn0 + 4);

    for (int kt = 0; kt < DD; kt += BK) {
        As[lkh + 0][lm] = pa.x * wv;
        As[lkh + 1][lm] = pa.y * wv;
        As[lkh + 2][lm] = pa.z * wv;
        As[lkh + 3][lm] = pa.w * wv;
        *(float4*)&Bs[bk0][bn0]     = pb0;
        *(float4*)&Bs[bk0][bn0 + 4] = pb1;
        __syncthreads();
        if (kt + BK < DD) {
            pa  = *(const float4*)(arow + kt + BK + lkh);
            pb0 = *(const float4*)(bbase + (size_t)(kt + BK + bk0) * (NE * NS) + bn0);
            pb1 = *(const float4*)(bbase + (size_t)(kt + BK + bk0) * (NE * NS) + bn0 + 4);
        }
#pragma unroll
        for (int k = 0; k < BK; k++) {
            float4 a = *(const float4*)&As[k][mt];
            ulonglong2 b0 = *(const ulonglong2*)&Bs[k][nt];
            ulonglong2 b1 = *(const ulonglong2*)&Bs[k][nt + 4];
            unsigned long long bb0 = b0.x, bb1 = b0.y, bb2 = b1.x, bb3 = b1.y;
            float av[4] = {a.x, a.y, a.z, a.w};
#pragma unroll
            for (int i = 0; i < 4; i++) {
                unsigned long long ad = pack2(av[i], av[i]);
                fma2(acc[i][0], ad, bb0);
                fma2(acc[i][1], ad, bb1);
                fma2(acc[i][2], ad, bb2);
                fma2(acc[i][3], ad, bb3);
            }
        }
        __syncthreads();
    }

    float bias[8];
#pragma unroll
    for (int j = 0; j < 8; j++) bias[j] = f1b[e * NS + nt + j];
    float* orow = g_inner + ((size_t)e * NG + gbase) * NS;
#pragma unroll
    for (int i = 0; i < 4; i++) {
        float o[8];
#pragma unroll
        for (int j = 0; j < 4; j++) {
            float2 v = unpack2(acc[i][j]);
            o[2 * j]     = fmaxf(v.x + bias[2 * j],     0.f);
            o[2 * j + 1] = fmaxf(v.y + bias[2 * j + 1], 0.f);
        }
        size_t off = (size_t)(mt + i) * NS + nt;
        *(float4*)&orow[off]     = make_float4(o[0], o[1], o[2], o[3]);
        *(float4*)&orow[off + 4] = make_float4(o[4], o[5], o[6], o[7]);
    }
}

// ---------------------------------------------------------------------------
// FF2 + combine: per expert, Y = INNER[e] @ f2[e]; out[token(g,e),:] += w*Y[g,:]
// Batched GEMM M=512 K=128 N=1024. Block tile 128x128, BK=16, 8x8 micro.
// ---------------------------------------------------------------------------
__global__ __launch_bounds__(256, 2) void gemm2_kernel(
    const float* __restrict__ f2, float* __restrict__ out)
{
    const int BM = 128, BN = 128, BK = 16;
    __shared__ __align__(16) float As[BK][BM];
    __shared__ __align__(16) float Bs[BK][BN];
    int e     = blockIdx.z;
    int gbase = blockIdx.x * BM;
    int nbase = blockIdx.y * BN;
    int tid   = threadIdx.x;

    int lm  = tid & 127;
    int lkh = (tid >> 7) << 3;       // 0 or 8
    const float* arow = g_inner + ((size_t)e * NG + gbase + lm) * NS;

    int bf  = tid << 1;
    int bk0 = bf >> 5;
    int bn0 = (bf & 31) << 2;
    const float* bbase = f2 + (size_t)e * NS * DD + nbase;

    unsigned long long acc[8][4];
#pragma unroll
    for (int i = 0; i < 8; i++)
#pragma unroll
        for (int j = 0; j < 4; j++) acc[i][j] = 0ULL;

    int mt = (tid >> 4) << 3;
    int nt = (tid & 15) << 3;

    float4 pa0 = *(const float4*)(arow + lkh);
    float4 pa1 = *(const float4*)(arow + lkh + 4);
    float4 pb0 = *(const float4*)(bbase + (size_t)bk0 * DD + bn0);
    float4 pb1 = *(const float4*)(bbase + (size_t)bk0 * DD + bn0 + 4);

    for (int kt = 0; kt < NS; kt += BK) {
        As[lkh + 0][lm] = pa0.x; As[lkh + 1][lm] = pa0.y;
        As[lkh + 2][lm] = pa0.z; As[lkh + 3][lm] = pa0.w;
        As[lkh + 4][lm] = pa1.x; As[lkh + 5][lm] = pa1.y;
        As[lkh + 6][lm] = pa1.z; As[lkh + 7][lm] = pa1.w;
        *(float4*)&Bs[bk0][bn0]     = pb0;
        *(float4*)&Bs[bk0][bn0 + 4] = pb1;
        __syncthreads();
        if (kt + BK < NS) {
            pa0 = *(const float4*)(arow + kt + BK + lkh);
            pa1 = *(const float4*)(arow + kt + BK + lkh + 4);
            pb0 = *(const float4*)(bbase + (size_t)(kt + BK + bk0) * DD + bn0);
            pb1 = *(const float4*)(bbase + (size_t)(kt + BK + bk0) * DD + bn0 + 4);
        }
#pragma unroll
        for (int k = 0; k < BK; k++) {
            float4 a0 = *(const float4*)&As[k][mt];
            float4 a1 = *(const float4*)&As[k][mt + 4];
            ulonglong2 b0 = *(const ulonglong2*)&Bs[k][nt];
            ulonglong2 b1 = *(const ulonglong2*)&Bs[k][nt + 4];
            unsigned long long bb0 = b0.x, bb1 = b0.y, bb2 = b1.x, bb3 = b1.y;
            float av[8] = {a0.x, a0.y, a0.z, a0.w, a1.x, a1.y, a1.z, a1.w};
#pragma unroll
            for (int i = 0; i < 8; i++) {
                unsigned long long ad = pack2(av[i], av[i]);
                fma2(acc[i][0], ad, bb0);
                fma2(acc[i][1], ad, bb1);
                fma2(acc[i][2], ad, bb2);
                fma2(acc[i][3], ad, bb3);
            }
        }
        __syncthreads();
    }

#pragma unroll
    for (int i = 0; i < 8; i++) {
        int gg  = gbase + mt + i;
        int tok = gg * TG + g_sel[gg * NE + e];
        float wv = g_w[gg * NE + e];
        float* orow = out + (size_t)tok * DD + nbase + nt;
#pragma unroll
        for (int j = 0; j < 4; j++) {
            float2 v = unpack2(acc[i][j]);
            atomicAdd(&orow[2 * j],     wv * v.x);
            atomicAdd(&orow[2 * j + 1], wv * v.y);
        }
    }
}

// ---------------------------------------------------------------------------
extern "C" void kernel_launch(void* const* d_in, const int* in_sizes, int n_in,
                              void* d_out, int out_size) {
    const float* x    = (const float*)d_in[0];
    const float* ctrl = (const float*)d_in[1];
    const float* f1   = (const float*)d_in[2];
    const float* f2   = (const float*)d_in[3];
    const float* f1b  = (const float*)d_in[4];
    float* out = (float*)d_out;

    cudaMemsetAsync(out, 0, (size_t)out_size * sizeof(float), 0);
    router_kernel<<<NG, 256>>>(x, ctrl);
    gemm1_kernel<<<dim3(NG / 64, NE), 256>>>(x, f1, f1b);
    gemm2_kernel<<<dim3(NG / 128, DD / 128, NE), 256>>>(f2, out);
}

// round 2
// speedup vs baseline: 1.5616x; 1.5616x over previous
#include <cuda_runtime.h>

#define NG 512   // total groups (4 * 4096/32)
#define TG 32    // tokens per group
#define DD 1024  // model dim
#define NE 32    // experts
#define NS 128   // expert hidden size

__device__ float g_w[NG * NE];
__device__ int   g_sel[NG * NE];
__device__ float g_inner[(size_t)NE * NG * NS];  // 8 MB scratch

// ---- packed f32x2 helpers (FFMA2 only reachable via PTX) ----
static __device__ __forceinline__ unsigned long long pack2(float lo, float hi) {
    unsigned long long r;
    asm("mov.b64 %0, {%1, %2};" : "=l"(r) : "f"(lo), "f"(hi));
    return r;
}
static __device__ __forceinline__ void fma2(unsigned long long &d,
                                            unsigned long long a,
                                            unsigned long long b) {
    asm("fma.rn.f32x2 %0, %1, %2, %0;" : "+l"(d) : "l"(a), "l"(b));
}
static __device__ __forceinline__ float2 unpack2(unsigned long long v) {
    float lo, hi;
    asm("mov.b64 {%0, %1}, %2;" : "=f"(lo), "=f"(hi) : "l"(v));
    return make_float2(lo, hi);
}

// ---------------------------------------------------------------------------
// Router: register-blocked GEMM over 128 tokens x 32 experts per CTA.
// Micro-tile 4 tokens x 4 experts, LDS.128 on both operands, f32x2 FMAs.
// Then per-(group,expert) argmax + softmax weight.
// ---------------------------------------------------------------------------
#define RT 128   // tokens per block (4 groups)
#define RDC 64   // d-chunk
#define XPAD 68  // xs row stride (keeps 16B alignment, breaks bank patterns)

__global__ __launch_bounds__(256) void router_kernel(
    const float* __restrict__ x, const float* __restrict__ ctrl)
{
    __shared__ __align__(16) float xs[RT * XPAD];  // [t][d], aliased as Ls later
    __shared__ __align__(16) float cs[RDC][NE];
    int tid = threadIdx.x;
    int tokbase = blockIdx.x * RT;

    int mt = (tid >> 3) << 2;   // token offset 0..124
    int et = (tid & 7) << 2;    // expert offset 0..28

    unsigned long long acc[4][2];
#pragma unroll
    for (int i = 0; i < 4; i++) { acc[i][0] = 0ULL; acc[i][1] = 0ULL; }

    for (int dc = 0; dc < DD; dc += RDC) {
        __syncthreads();
        // x chunk: 128 tokens x 64 d (16 lanes cover one token's 64 floats)
#pragma unroll
        for (int it = 0; it < 8; it++) {
            int t  = (tid >> 4) + (it << 4);
            int d4 = (tid & 15) << 2;
            *(float4*)&xs[t * XPAD + d4] =
                *(const float4*)(x + (size_t)(tokbase + t) * DD + dc + d4);
        }
        // ctrl chunk: 64 d x 32 e
#pragma unroll
        for (int it = 0; it < 2; it++) {
            int q  = tid + (it << 8);       // float4 slot 0..511
            int d  = q >> 3;
            int e4 = (q & 7) << 2;
            *(float4*)&cs[d][e4] = *(const float4*)(ctrl + (size_t)(dc + d) * NE + e4);
        }
        __syncthreads();
#pragma unroll 4
        for (int d = 0; d < RDC; d += 4) {
            float4 xr[4];
#pragma unroll
            for (int i = 0; i < 4; i++)
                xr[i] = *(const float4*)&xs[(mt + i) * XPAD + d];
#pragma unroll
            for (int dd = 0; dd < 4; dd++) {
                ulonglong2 cb = *(const ulonglong2*)&cs[d + dd][et];
                float xv[4] = {0.f, 0.f, 0.f, 0.f};
                xv[0] = (dd == 0) ? xr[0].x : (dd == 1) ? xr[0].y : (dd == 2) ? xr[0].z : xr[0].w;
                xv[1] = (dd == 0) ? xr[1].x : (dd == 1) ? xr[1].y : (dd == 2) ? xr[1].z : xr[1].w;
                xv[2] = (dd == 0) ? xr[2].x : (dd == 1) ? xr[2].y : (dd == 2) ? xr[2].z : xr[2].w;
                xv[3] = (dd == 0) ? xr[3].x : (dd == 1) ? xr[3].y : (dd == 2) ? xr[3].z : xr[3].w;
#pragma unroll
                for (int i = 0; i < 4; i++) {
                    unsigned long long ad = pack2(xv[i], xv[i]);
                    fma2(acc[i][0], ad, cb.x);
                    fma2(acc[i][1], ad, cb.y);
                }
            }
        }
    }
    __syncthreads();

    // write logits (+tie-break) into aliased smem
    float* Ls = xs;                       // [t][e], 4096 floats <= 8704
    const float step = 1e-6f / 31.0f;
#pragma unroll
    for (int i = 0; i < 4; i++) {
        int t = mt + i;
        float tb = (float)(t & 31) * step;
        float2 v0 = unpack2(acc[i][0]);
        float2 v1 = unpack2(acc[i][1]);
        Ls[t * NE + et + 0] = v0.x + tb;
        Ls[t * NE + et + 1] = v0.y + tb;
        Ls[t * NE + et + 2] = v1.x + tb;
        Ls[t * NE + et + 3] = v1.y + tb;
    }
    __syncthreads();

    if (tid < 128) {
        int gq = tid >> 5;
        int e  = tid & 31;
        int g  = blockIdx.x * 4 + gq;
        float m = Ls[(gq * TG) * NE + e];
        int am = 0;
#pragma unroll
        for (int t = 1; t < TG; t++) {
            float v = Ls[(gq * TG + t) * NE + e];
            if (v > m) { m = v; am = t; }
        }
        float s = 0.f;
#pragma unroll
        for (int t = 0; t < TG; t++) s += __expf(Ls[(gq * TG + t) * NE + e] - m);
        g_w[g * NE + e]   = 1.0f / s;
        g_sel[g * NE + e] = am;
    }
}

// ---------------------------------------------------------------------------
// FF1: per expert e, INNER = relu( (w * x[sel]) @ f1[:,e,:] + f1b[e,:] )
// Batched GEMM M=512 K=1024 N=128. Tile 128x128, BK=16, 256 thr, 8x8 micro.
// ---------------------------------------------------------------------------
__global__ __launch_bounds__(256, 2) void gemm1_kernel(
    const float* __restrict__ x, const float* __restrict__ f1,
    const float* __restrict__ f1b)
{
    const int BK = 16;
    __shared__ __align__(16) float As[BK][128];
    __shared__ __align__(16) float Bs[BK][128];
    int e     = blockIdx.y;
    int gbase = blockIdx.x * 128;
    int tid   = threadIdx.x;

    // A loader: gathered + scaled rows
    int lm = tid & 127;
    int kh = (tid >> 7) << 3;        // 0 or 8
    int gg = gbase + lm;
    float wv = g_w[gg * NE + e];
    const float* arow = x + (size_t)(gg * TG + g_sel[gg * NE + e]) * DD;

    // B loader: f1[k, e, n], row stride NE*NS
    int bk = tid >> 4;               // 0..15
    int bn = (tid & 15) << 3;        // 0..120
    const float* bcol = f1 + (size_t)e * NS + bn;

    unsigned long long acc[8][4];
#pragma unroll
    for (int i = 0; i < 8; i++)
#pragma unroll
        for (int j = 0; j < 4; j++) acc[i][j] = 0ULL;

    int mt = (tid >> 4) << 3;
    int nt = (tid & 15) << 3;

    float4 pa0 = *(const float4*)(arow + kh);
    float4 pa1 = *(const float4*)(arow + kh + 4);
    float4 pb0 = *(const float4*)(bcol + (size_t)bk * (NE * NS));
    float4 pb1 = *(const float4*)(bcol + (size_t)bk * (NE * NS) + 4);

    for (int kt = 0; kt < DD; kt += BK) {
        As[kh + 0][lm] = pa0.x * wv; As[kh + 1][lm] = pa0.y * wv;
        As[kh + 2][lm] = pa0.z * wv; As[kh + 3][lm] = pa0.w * wv;
        As[kh + 4][lm] = pa1.x * wv; As[kh + 5][lm] = pa1.y * wv;
        As[kh + 6][lm] = pa1.z * wv; As[kh + 7][lm] = pa1.w * wv;
        *(float4*)&Bs[bk][bn]     = pb0;
        *(float4*)&Bs[bk][bn + 4] = pb1;
        __syncthreads();
        if (kt + BK < DD) {
            pa0 = *(const float4*)(arow + kt + BK + kh);
            pa1 = *(const float4*)(arow + kt + BK + kh + 4);
            pb0 = *(const float4*)(bcol + (size_t)(kt + BK + bk) * (NE * NS));
            pb1 = *(const float4*)(bcol + (size_t)(kt + BK + bk) * (NE * NS) + 4);
        }
#pragma unroll
        for (int k = 0; k < BK; k++) {
            float4 a0 = *(const float4*)&As[k][mt];
            float4 a1 = *(const float4*)&As[k][mt + 4];
            ulonglong2 b0 = *(const ulonglong2*)&Bs[k][nt];
            ulonglong2 b1 = *(const ulonglong2*)&Bs[k][nt + 4];
            float av[8] = {a0.x, a0.y, a0.z, a0.w, a1.x, a1.y, a1.z, a1.w};
#pragma unroll
            for (int i = 0; i < 8; i++) {
                unsigned long long ad = pack2(av[i], av[i]);
                fma2(acc[i][0], ad, b0.x);
                fma2(acc[i][1], ad, b0.y);
                fma2(acc[i][2], ad, b1.x);
                fma2(acc[i][3], ad, b1.y);
            }
        }
        __syncthreads();
    }

    float bias[8];
#pragma unroll
    for (int j = 0; j < 8; j++) bias[j] = f1b[e * NS + nt + j];
    float* obase = g_inner + ((size_t)e * NG + gbase) * NS;
#pragma unroll
    for (int i = 0; i < 8; i++) {
        float o[8];
#pragma unroll
        for (int j = 0; j < 4; j++) {
            float2 v = unpack2(acc[i][j]);
            o[2 * j]     = fmaxf(v.x + bias[2 * j],     0.f);
            o[2 * j + 1] = fmaxf(v.y + bias[2 * j + 1], 0.f);
        }
        size_t off = (size_t)(mt + i) * NS + nt;
        *(float4*)&obase[off]     = make_float4(o[0], o[1], o[2], o[3]);
        *(float4*)&obase[off + 4] = make_float4(o[4], o[5], o[6], o[7]);
    }
}

// ---------------------------------------------------------------------------
// FF2 + combine: Y = INNER[e] @ f2[e]; out[token(g,e),:] += w*Y via red.v4
// Batched GEMM M=512 K=128 N=1024. Tile 128x128, BK=16, 8x8 micro.
// ---------------------------------------------------------------------------
__global__ __launch_bounds__(256, 2) void gemm2_kernel(
    const float* __restrict__ f2, float* __restrict__ out)
{
    const int BK = 16;
    __shared__ __align__(16) float As[BK][128];
    __shared__ __align__(16) float Bs[BK][128];
    int e     = blockIdx.z;
    int gbase = blockIdx.x * 128;
    int nbase = blockIdx.y * 128;
    int tid   = threadIdx.x;

    int lm = tid & 127;
    int kh = (tid >> 7) << 3;
    const float* arow = g_inner + ((size_t)e * NG + gbase + lm) * NS;

    int bk = tid >> 4;
    int bn = (tid & 15) << 3;
    const float* bbase = f2 + (size_t)e * NS * DD + nbase + bn;

    unsigned long long acc[8][4];
#pragma unroll
    for (int i = 0; i < 8; i++)
#pragma unroll
        for (int j = 0; j < 4; j++) acc[i][j] = 0ULL;

    int mt = (tid >> 4) << 3;
    int nt = (tid & 15) << 3;

    float4 pa0 = *(const float4*)(arow + kh);
    float4 pa1 = *(const float4*)(arow + kh + 4);
    float4 pb0 = *(const float4*)(bbase + (size_t)bk * DD);
    float4 pb1 = *(const float4*)(bbase + (size_t)bk * DD + 4);

    for (int kt = 0; kt < NS; kt += BK) {
        As[kh + 0][lm] = pa0.x; As[kh + 1][lm] = pa0.y;
        As[kh + 2][lm] = pa0.z; As[kh + 3][lm] = pa0.w;
        As[kh + 4][lm] = pa1.x; As[kh + 5][lm] = pa1.y;
        As[kh + 6][lm] = pa1.z; As[kh + 7][lm] = pa1.w;
        *(float4*)&Bs[bk][bn]     = pb0;
        *(float4*)&Bs[bk][bn + 4] = pb1;
        __syncthreads();
        if (kt + BK < NS) {
            pa0 = *(const float4*)(arow + kt + BK + kh);
            pa1 = *(const float4*)(arow + kt + BK + kh + 4);
            pb0 = *(const float4*)(bbase + (size_t)(kt + BK + bk) * DD);
            pb1 = *(const float4*)(bbase + (size_t)(kt + BK + bk) * DD + 4);
        }
#pragma unroll
        for (int k = 0; k < BK; k++) {
            float4 a0 = *(const float4*)&As[k][mt];
            float4 a1 = *(const float4*)&As[k][mt + 4];
            ulonglong2 b0 = *(const ulonglong2*)&Bs[k][nt];
            ulonglong2 b1 = *(const ulonglong2*)&Bs[k][nt + 4];
            float av[8] = {a0.x, a0.y, a0.z, a0.w, a1.x, a1.y, a1.z, a1.w};
#pragma unroll
            for (int i = 0; i < 8; i++) {
                unsigned long long ad = pack2(av[i], av[i]);
                fma2(acc[i][0], ad, b0.x);
                fma2(acc[i][1], ad, b0.y);
                fma2(acc[i][2], ad, b1.x);
                fma2(acc[i][3], ad, b1.y);
            }
        }
        __syncthreads();
    }

#pragma unroll
    for (int i = 0; i < 8; i++) {
        int gg  = gbase + mt + i;
        int tok = gg * TG + g_sel[gg * NE + e];
        float wv = g_w[gg * NE + e];
        float* orow = out + (size_t)tok * DD + nbase + nt;
        float2 v0 = unpack2(acc[i][0]);
        float2 v1 = unpack2(acc[i][1]);
        float2 v2 = unpack2(acc[i][2]);
        float2 v3 = unpack2(acc[i][3]);
        asm volatile("red.global.add.v4.f32 [%0], {%1, %2, %3, %4};"
                     :: "l"(orow), "f"(wv * v0.x), "f"(wv * v0.y),
                        "f"(wv * v1.x), "f"(wv * v1.y) : "memory");
        asm volatile("red.global.add.v4.f32 [%0], {%1, %2, %3, %4};"
                     :: "l"(orow + 4), "f"(wv * v2.x), "f"(wv * v2.y),
                        "f"(wv * v3.x), "f"(wv * v3.y) : "memory");
    }
}

// ---------------------------------------------------------------------------
extern "C" void kernel_launch(void* const* d_in, const int* in_sizes, int n_in,
                              void* d_out, int out_size) {
    const float* x    = (const float*)d_in[0];
    const float* ctrl = (const float*)d_in[1];
    const float* f1   = (const float*)d_in[2];
    const float* f2   = (const float*)d_in[3];
    const float* f1b  = (const float*)d_in[4];
    float* out = (float*)d_out;

    cudaMemsetAsync(out, 0, (size_t)out_size * sizeof(float), 0);
    router_kernel<<<NG / 4, 256>>>(x, ctrl);
    gemm1_kernel<<<dim3(NG / 128, NE), 256>>>(x, f1, f1b);
    gemm2_kernel<<<dim3(NG / 128, DD / 128, NE), 256>>>(f2, out);
}